// round 2
// baseline (speedup 1.0000x reference)
#include <cuda_runtime.h>
#include <cuda_bf16.h>
#include <cstdint>

#define HDIM  1024
#define BATCH 16384
#define BM    128
#define BN    128
#define BK    16
#define LDA_S 20      // floats per smem A row (80B, conflict-free fragment LDS)
#define LDB_S 136     // floats per smem B row (544B, conflict-free fragment LDS)
#define NT    (HDIM / BK)

// 64MB fp32 scratch for t = state_inp * reset  (static __device__ array: allowed)
__device__ float g_t[(size_t)BATCH * HDIM];

static __device__ __forceinline__ float tf32r(float x) {
    float r;
    asm("cvt.rna.tf32.f32 %0, %1;" : "=f"(r) : "f"(x));
    return r;
}
static __device__ __forceinline__ void mma_tf32(float* c, const float* a, const float* b) {
    const uint32_t* au = reinterpret_cast<const uint32_t*>(a);
    const uint32_t* bu = reinterpret_cast<const uint32_t*>(b);
    asm volatile("mma.sync.aligned.m16n8k8.row.col.f32.tf32.tf32.f32 "
                 "{%0,%1,%2,%3}, {%4,%5,%6,%7}, {%8,%9}, {%0,%1,%2,%3};"
                 : "+f"(c[0]), "+f"(c[1]), "+f"(c[2]), "+f"(c[3])
                 : "r"(au[0]), "r"(au[1]), "r"(au[2]), "r"(au[3]), "r"(bu[0]), "r"(bu[1]));
}

// ---------------------------------------------------------------------------
// Shared GEMM core: C[128x128] = A[128x1024] @ B[1024x128] with double buffer.
// A_ld / B_ld: functors returning float4 for given (row, kcol4) / (krow, col4).
// ---------------------------------------------------------------------------
template <typename LoadA, typename LoadB>
static __device__ __forceinline__ void gemm_core(float acc[4][4][4], LoadA loadA, LoadB loadB,
                                                 float (*As)[BM][LDA_S], float (*Bs)[BK][LDB_S]) {
    const int tid  = threadIdx.x;
    const int lane = tid & 31;
    const int warp = tid >> 5;
    const int wr   = warp >> 2;   // 0..1
    const int wc   = warp & 3;    // 0..3

    // ---- G2S tile 0 ----
#pragma unroll
    for (int i = 0; i < 2; i++) {
        int idx = tid + i * 256;
        int r = idx >> 2, c4 = (idx & 3) * 4;
        float4 v = loadA(r, 0 + c4);
        As[0][r][c4] = tf32r(v.x); As[0][r][c4 + 1] = tf32r(v.y);
        As[0][r][c4 + 2] = tf32r(v.z); As[0][r][c4 + 3] = tf32r(v.w);
    }
#pragma unroll
    for (int i = 0; i < 2; i++) {
        int idx = tid + i * 256;
        int r = idx >> 5, c4 = (idx & 31) * 4;
        float4 v = loadB(0 + r, c4);
        Bs[0][r][c4] = tf32r(v.x); Bs[0][r][c4 + 1] = tf32r(v.y);
        Bs[0][r][c4 + 2] = tf32r(v.z); Bs[0][r][c4 + 3] = tf32r(v.w);
    }
    __syncthreads();

    float4 ra[2], rb[2];
    for (int kt = 0; kt < NT; ++kt) {
        const int buf = kt & 1;
        if (kt + 1 < NT) {
            const int k0 = (kt + 1) * BK;
#pragma unroll
            for (int i = 0; i < 2; i++) {
                int idx = tid + i * 256;
                int r = idx >> 2, c4 = (idx & 3) * 4;
                ra[i] = loadA(r, k0 + c4);
            }
#pragma unroll
            for (int i = 0; i < 2; i++) {
                int idx = tid + i * 256;
                int r = idx >> 5, c4 = (idx & 31) * 4;
                rb[i] = loadB(k0 + r, c4);
            }
        }
#pragma unroll
        for (int ks = 0; ks < 2; ks++) {
            const int kk = ks * 8;
            float af[4][4], bf[4][2];
#pragma unroll
            for (int mi = 0; mi < 4; mi++) {
                const int row = wr * 64 + mi * 16 + (lane >> 2);
                const int col = kk + (lane & 3);
                af[mi][0] = As[buf][row][col];
                af[mi][1] = As[buf][row + 8][col];
                af[mi][2] = As[buf][row][col + 4];
                af[mi][3] = As[buf][row + 8][col + 4];
            }
#pragma unroll
            for (int ni = 0; ni < 4; ni++) {
                const int col = wc * 32 + ni * 8 + (lane >> 2);
                bf[ni][0] = Bs[buf][kk + (lane & 3)][col];
                bf[ni][1] = Bs[buf][kk + (lane & 3) + 4][col];
            }
#pragma unroll
            for (int mi = 0; mi < 4; mi++)
#pragma unroll
                for (int ni = 0; ni < 4; ni++)
                    mma_tf32(acc[mi][ni], af[mi], bf[ni]);
        }
        if (kt + 1 < NT) {
            const int nb = buf ^ 1;
#pragma unroll
            for (int i = 0; i < 2; i++) {
                int idx = tid + i * 256;
                int r = idx >> 2, c4 = (idx & 3) * 4;
                As[nb][r][c4] = tf32r(ra[i].x); As[nb][r][c4 + 1] = tf32r(ra[i].y);
                As[nb][r][c4 + 2] = tf32r(ra[i].z); As[nb][r][c4 + 3] = tf32r(ra[i].w);
            }
#pragma unroll
            for (int i = 0; i < 2; i++) {
                int idx = tid + i * 256;
                int r = idx >> 5, c4 = (idx & 31) * 4;
                Bs[nb][r][c4] = tf32r(rb[i].x); Bs[nb][r][c4 + 1] = tf32r(rb[i].y);
                Bs[nb][r][c4 + 2] = tf32r(rb[i].z); Bs[nb][r][c4 + 3] = tf32r(rb[i].w);
            }
        }
        __syncthreads();
    }
}

// ---------------------------------------------------------------------------
// Kernel 1: t = state_inp * sigmoid(prev @ Wur[:,H:2H] + inp[:,2H:3H])  (fp32)
// ---------------------------------------------------------------------------
__global__ __launch_bounds__(256) void ggru_gemm1(
    const float* __restrict__ prev, const float* __restrict__ Wur,
    const float* __restrict__ inp)
{
    __shared__ float As[2][BM][LDA_S];
    __shared__ float Bs[2][BK][LDB_S];

    const int lane = threadIdx.x & 31;
    const int warp = threadIdx.x >> 5;
    const int wr = warp >> 2, wc = warp & 3;
    const int mBase = blockIdx.y * BM;
    const int nBase = blockIdx.x * BN;
    const float* Wp = Wur + HDIM;  // reset-gate columns
    const int ldw = 2 * HDIM;

    float acc[4][4][4];
#pragma unroll
    for (int i = 0; i < 4; i++)
#pragma unroll
        for (int j = 0; j < 4; j++)
#pragma unroll
            for (int k = 0; k < 4; k++) acc[i][j][k] = 0.f;

    auto loadA = [&](int r, int kc) {
        return *reinterpret_cast<const float4*>(prev + (size_t)(mBase + r) * HDIM + kc);
    };
    auto loadB = [&](int kr, int c) {
        return *reinterpret_cast<const float4*>(Wp + (size_t)kr * ldw + nBase + c);
    };
    gemm_core(acc, loadA, loadB, As, Bs);

    // ---- epilogue: sigmoid + multiply, store fp32 (tf32-rounded) t ----
#pragma unroll
    for (int mi = 0; mi < 4; mi++) {
#pragma unroll
        for (int ni = 0; ni < 4; ni++) {
            const int r0 = mBase + wr * 64 + mi * 16 + (lane >> 2);
            const int c0 = nBase + wc * 32 + ni * 8 + (lane & 3) * 2;
#pragma unroll
            for (int j = 0; j < 2; j++) {
                const int row = r0 + j * 8;
                const float* irow = inp + (size_t)row * (3 * HDIM);
                float2 g = *reinterpret_cast<const float2*>(irow + 2 * HDIM + c0);
                float2 s = *reinterpret_cast<const float2*>(irow + c0);
                float x0 = acc[mi][ni][j * 2 + 0] + g.x;
                float x1 = acc[mi][ni][j * 2 + 1] + g.y;
                float2 t;
                t.x = tf32r(s.x * (1.f / (1.f + __expf(-x0))));
                t.y = tf32r(s.y * (1.f / (1.f + __expf(-x1))));
                *reinterpret_cast<float2*>(&g_t[(size_t)row * HDIM + c0]) = t;
            }
        }
    }
}

// ---------------------------------------------------------------------------
// Kernel 2: out = prev + mask * (tanh(t @ U + state_inp) + 1)
// ---------------------------------------------------------------------------
__global__ __launch_bounds__(256) void ggru_gemm2(
    const float* __restrict__ inp, const float* __restrict__ prev,
    const float* __restrict__ mask, const float* __restrict__ U,
    float* __restrict__ out)
{
    __shared__ float As[2][BM][LDA_S];
    __shared__ float Bs[2][BK][LDB_S];

    const int lane = threadIdx.x & 31;
    const int warp = threadIdx.x >> 5;
    const int wr = warp >> 2, wc = warp & 3;
    const int mBase = blockIdx.y * BM;
    const int nBase = blockIdx.x * BN;

    float acc[4][4][4];
#pragma unroll
    for (int i = 0; i < 4; i++)
#pragma unroll
        for (int j = 0; j < 4; j++)
#pragma unroll
            for (int k = 0; k < 4; k++) acc[i][j][k] = 0.f;

    auto loadA = [&](int r, int kc) {
        return *reinterpret_cast<const float4*>(g_t + (size_t)(mBase + r) * HDIM + kc);
    };
    auto loadB = [&](int kr, int c) {
        return *reinterpret_cast<const float4*>(U + (size_t)kr * HDIM + nBase + c);
    };
    gemm_core(acc, loadA, loadB, As, Bs);

    // ---- epilogue: tanh + gated blend ----
#pragma unroll
    for (int mi = 0; mi < 4; mi++) {
#pragma unroll
        for (int ni = 0; ni < 4; ni++) {
            const int r0 = mBase + wr * 64 + mi * 16 + (lane >> 2);
            const int c0 = nBase + wc * 32 + ni * 8 + (lane & 3) * 2;
#pragma unroll
            for (int j = 0; j < 2; j++) {
                const int row = r0 + j * 8;
                float2 s  = *reinterpret_cast<const float2*>(inp + (size_t)row * (3 * HDIM) + c0);
                float2 pv = *reinterpret_cast<const float2*>(prev + (size_t)row * HDIM + c0);
                float mk = mask[row];
                float n0 = tanhf(acc[mi][ni][j * 2 + 0] + s.x);
                float n1 = tanhf(acc[mi][ni][j * 2 + 1] + s.y);
                float2 o;
                o.x = pv.x + mk * (n0 + 1.f);
                o.y = pv.y + mk * (n1 + 1.f);
                *reinterpret_cast<float2*>(out + (size_t)row * HDIM + c0) = o;
            }
        }
    }
}

// ---------------------------------------------------------------------------
extern "C" void kernel_launch(void* const* d_in, const int* in_sizes, int n_in,
                              void* d_out, int out_size) {
    const float* inp  = (const float*)d_in[0];   // [16384, 3072]
    const float* prev = (const float*)d_in[1];   // [16384, 1024]
    const float* mask = (const float*)d_in[2];   // [16384]
    const float* Wur  = (const float*)d_in[3];   // [1024, 2048]
    const float* U    = (const float*)d_in[4];   // [1024, 1024]
    float* out = (float*)d_out;                  // [16384, 1024]

    dim3 grid(HDIM / BN, BATCH / BM);            // (8, 128)
    ggru_gemm1<<<grid, 256>>>(prev, Wur, inp);
    ggru_gemm2<<<grid, 256>>>(inp, prev, mask, U, out);
}

// round 8
// speedup vs baseline: 1.5288x; 1.5288x over previous
#include <cuda_runtime.h>
#include <cstdint>

#define H       1024
#define BATCH   16384
#define BM      128
#define BN      128
#define BK      32
#define NT      (H / BK)            // 32
#define STAGES  3
#define A_BYTES (BM * BK * 4)       // 16KB
#define B_BYTES (BN * BK * 4)       // 16KB
#define STG_BYTES (A_BYTES + B_BYTES)          // 32KB
#define SMEM_TOTAL (STAGES * STG_BYTES)        // 96KB

// scratch (__device__ globals: allowed)
__device__ float g_t[(size_t)BATCH * H];     // 64MB intermediate
__device__ float g_WrT[(size_t)H * H];       // Wur[:,H:2H]^T (tf32-rounded)
__device__ float g_UT[(size_t)H * H];        // U^T (tf32-rounded)

static __device__ __forceinline__ uint32_t smem_u32(const void* p) {
    return (uint32_t)__cvta_generic_to_shared(p);
}
static __device__ __forceinline__ float tf32r(float x) {
    float r; asm("cvt.rna.tf32.f32 %0, %1;" : "=f"(r) : "f"(x)); return r;
}
static __device__ __forceinline__ void cp16(uint32_t dst, const void* src) {
    asm volatile("cp.async.cg.shared.global [%0], [%1], 16;" :: "r"(dst), "l"(src));
}
#define CP_COMMIT() asm volatile("cp.async.commit_group;" ::: "memory")
#define CP_WAIT(n)  asm volatile("cp.async.wait_group %0;" :: "n"(n) : "memory")

static __device__ __forceinline__ void ldsm_x4(uint32_t* r, uint32_t a) {
    asm volatile("ldmatrix.sync.aligned.m8n8.x4.shared.b16 {%0,%1,%2,%3}, [%4];"
                 : "=r"(r[0]), "=r"(r[1]), "=r"(r[2]), "=r"(r[3]) : "r"(a));
}
static __device__ __forceinline__ void mma_tf32(float* c, const uint32_t* a, const uint32_t* b) {
    asm volatile("mma.sync.aligned.m16n8k8.row.col.f32.tf32.tf32.f32 "
                 "{%0,%1,%2,%3}, {%4,%5,%6,%7}, {%8,%9}, {%0,%1,%2,%3};"
                 : "+f"(c[0]), "+f"(c[1]), "+f"(c[2]), "+f"(c[3])
                 : "r"(a[0]), "r"(a[1]), "r"(a[2]), "r"(a[3]), "r"(b[0]), "r"(b[1]));
}

// ---------------------------------------------------------------------------
// stage loader: A tile [128 x 32] + B tile [128 x 32] (fp32, SW128 swizzled)
// ---------------------------------------------------------------------------
static __device__ __forceinline__ void load_stage(uint32_t stageBase,
        const float* __restrict__ Ag, int m0,
        const float* __restrict__ Bg, int n0, int k0, int tid)
{
#pragma unroll
    for (int j = 0; j < 4; j++) {
        int idx = tid + j * 256;
        int r = idx >> 3, c = idx & 7;
        uint32_t off = (uint32_t)idx * 16;
        uint32_t sw = off ^ ((off >> 3) & 0x70);
        cp16(stageBase + sw, Ag + (size_t)(m0 + r) * H + k0 + c * 4);
    }
#pragma unroll
    for (int j = 0; j < 4; j++) {
        int idx = tid + j * 256;
        int r = idx >> 3, c = idx & 7;
        uint32_t off = (uint32_t)idx * 16;
        uint32_t sw = off ^ ((off >> 3) & 0x70);
        cp16(stageBase + A_BYTES + sw, Bg + (size_t)(n0 + r) * H + k0 + c * 4);
    }
}

// ---------------------------------------------------------------------------
// GEMM core: acc[4][4][4] += A[128x1024] @ B[1024x128]^T   (B stored [n][k])
// 8 warps in 2(M) x 4(N); warp tile 64x32; ldmatrix-fed tf32 HMMA.
// ---------------------------------------------------------------------------
static __device__ __forceinline__ void gemm_core(float acc[4][4][4],
        const float* __restrict__ Ag, const float* __restrict__ Bg,
        int m0, int n0, char* smem)
{
    const uint32_t sb = smem_u32(smem);
    const int tid  = threadIdx.x;
    const int lane = tid & 31;
    const int warp = tid >> 5;
    const int wr   = warp >> 2;   // 0..1
    const int wc   = warp & 3;    // 0..3

    // ldmatrix per-lane geometry (fp32 rows of 128B, 16B chunks, SW128)
    // A: matrices (rows 0-7,k0-3)(rows 8-15,k0-3)(rows 0-7,k4-7)(rows 8-15,k4-7)
    const int a_r  = wr * 64 + (lane & 15);          // + mi*16
    const int a_cx = lane >> 4;                      // chunk half
    const int arx  = a_r & 7;                        // swizzle XOR (mi*16 invariant)
    // B: matrices (n 0-7,k0-3)(n 0-7,k4-7)(n 8-15,k0-3)(n 8-15,k4-7)
    const int b_r  = wc * 32 + ((lane >> 4) << 3) + (lane & 7);   // + g*16
    const int b_cx = (lane >> 3) & 1;
    const int brx  = b_r & 7;

#pragma unroll
    for (int i = 0; i < 4; i++)
#pragma unroll
        for (int j = 0; j < 4; j++)
#pragma unroll
            for (int k = 0; k < 4; k++) acc[i][j][k] = 0.f;

    // prologue: stages 0, 1
    load_stage(sb, Ag, m0, Bg, n0, 0, tid);
    CP_COMMIT();
    load_stage(sb + STG_BYTES, Ag, m0, Bg, n0, BK, tid);
    CP_COMMIT();

    for (int i = 0; i < NT; ++i) {
        const int s = i % STAGES;
        if (i == NT - 1) CP_WAIT(0); else CP_WAIT(1);
        __syncthreads();

        const uint32_t Abase = sb + s * STG_BYTES;
        const uint32_t Bbase = Abase + A_BYTES;
#pragma unroll
        for (int ks = 0; ks < 4; ks++) {
            uint32_t af[4][4], bf[4][2];
#pragma unroll
            for (int mi = 0; mi < 4; mi++) {
                uint32_t addr = Abase + (uint32_t)(a_r + mi * 16) * 128
                              + (uint32_t)((((ks << 1) + a_cx) ^ arx) << 4);
                ldsm_x4(af[mi], addr);
            }
#pragma unroll
            for (int g = 0; g < 2; g++) {
                uint32_t tmp[4];
                uint32_t addr = Bbase + (uint32_t)(b_r + g * 16) * 128
                              + (uint32_t)((((ks << 1) + b_cx) ^ brx) << 4);
                ldsm_x4(tmp, addr);
                bf[2 * g][0] = tmp[0]; bf[2 * g][1] = tmp[1];
                bf[2 * g + 1][0] = tmp[2]; bf[2 * g + 1][1] = tmp[3];
            }
#pragma unroll
            for (int mi = 0; mi < 4; mi++)
#pragma unroll
                for (int ni = 0; ni < 4; ni++)
                    mma_tf32(acc[mi][ni], af[mi], bf[ni]);
        }

        if (i + 2 < NT) {
            load_stage(sb + ((i + 2) % STAGES) * STG_BYTES,
                       Ag, m0, Bg, n0, (i + 2) * BK, tid);
            CP_COMMIT();
        }
    }
}

// ---------------------------------------------------------------------------
// transpose + tf32-round weights: g_WrT[n][k] = Wur[k][H+n], g_UT[n][k] = U[k][n]
// ---------------------------------------------------------------------------
__global__ __launch_bounds__(256) void ggru_transpose(
    const float* __restrict__ Wur, const float* __restrict__ U)
{
    __shared__ float tile[32][33];
    const int mat = blockIdx.z;
    const float* src = mat ? U : (Wur + H);
    const int lds = mat ? H : 2 * H;
    float* dst = mat ? g_UT : g_WrT;
    const int kBase = blockIdx.y * 32, nBase = blockIdx.x * 32;
    const int tx = threadIdx.x & 31, ty = threadIdx.x >> 5;   // 32 x 8

#pragma unroll
    for (int j = 0; j < 4; j++)
        tile[ty + j * 8][tx] = src[(size_t)(kBase + ty + j * 8) * lds + nBase + tx];
    __syncthreads();
#pragma unroll
    for (int j = 0; j < 4; j++)
        dst[(size_t)(nBase + ty + j * 8) * H + kBase + tx] = tf32r(tile[tx][ty + j * 8]);
}

// ---------------------------------------------------------------------------
// GEMM1: t = state_inp * sigmoid(prev @ Wr + gate_reset)
// ---------------------------------------------------------------------------
__global__ __launch_bounds__(256, 2) void ggru_gemm1(
    const float* __restrict__ prev, const float* __restrict__ inp)
{
    extern __shared__ __align__(1024) char smem[];
    const int m0 = blockIdx.y * BM, n0 = blockIdx.x * BN;
    float acc[4][4][4];
    gemm_core(acc, prev, g_WrT, m0, n0, smem);

    const int lane = threadIdx.x & 31, warp = threadIdx.x >> 5;
    const int wr = warp >> 2, wc = warp & 3;
#pragma unroll
    for (int mi = 0; mi < 4; mi++) {
#pragma unroll
        for (int ni = 0; ni < 4; ni++) {
            const int r0 = m0 + wr * 64 + mi * 16 + (lane >> 2);
            const int c0 = n0 + wc * 32 + ni * 8 + (lane & 3) * 2;
#pragma unroll
            for (int j = 0; j < 2; j++) {
                const int row = r0 + j * 8;
                const float* irow = inp + (size_t)row * (3 * H);
                float2 g = *reinterpret_cast<const float2*>(irow + 2 * H + c0);
                float2 s = *reinterpret_cast<const float2*>(irow + c0);
                float x0 = acc[mi][ni][j * 2 + 0] + g.x;
                float x1 = acc[mi][ni][j * 2 + 1] + g.y;
                float2 t;
                t.x = s.x * (1.f / (1.f + __expf(-x0)));
                t.y = s.y * (1.f / (1.f + __expf(-x1)));
                *reinterpret_cast<float2*>(&g_t[(size_t)row * H + c0]) = t;
            }
        }
    }
}

// ---------------------------------------------------------------------------
// GEMM2: out = prev + mask * (tanh(t @ U + state_inp) + 1)
// ---------------------------------------------------------------------------
__global__ __launch_bounds__(256, 2) void ggru_gemm2(
    const float* __restrict__ inp, const float* __restrict__ prev,
    const float* __restrict__ mask, float* __restrict__ out)
{
    extern __shared__ __align__(1024) char smem[];
    const int m0 = blockIdx.y * BM, n0 = blockIdx.x * BN;
    float acc[4][4][4];
    gemm_core(acc, g_t, g_UT, m0, n0, smem);

    const int lane = threadIdx.x & 31, warp = threadIdx.x >> 5;
    const int wr = warp >> 2, wc = warp & 3;
#pragma unroll
    for (int mi = 0; mi < 4; mi++) {
#pragma unroll
        for (int ni = 0; ni < 4; ni++) {
            const int r0 = m0 + wr * 64 + mi * 16 + (lane >> 2);
            const int c0 = n0 + wc * 32 + ni * 8 + (lane & 3) * 2;
#pragma unroll
            for (int j = 0; j < 2; j++) {
                const int row = r0 + j * 8;
                float2 s  = *reinterpret_cast<const float2*>(inp + (size_t)row * (3 * H) + c0);
                float2 pv = *reinterpret_cast<const float2*>(prev + (size_t)row * H + c0);
                float mk = mask[row];
                float n0v = tanhf(acc[mi][ni][j * 2 + 0] + s.x);
                float n1v = tanhf(acc[mi][ni][j * 2 + 1] + s.y);
                float2 o;
                o.x = pv.x + mk * (n0v + 1.f);
                o.y = pv.y + mk * (n1v + 1.f);
                *reinterpret_cast<float2*>(out + (size_t)row * H + c0) = o;
            }
        }
    }
}

// ---------------------------------------------------------------------------
extern "C" void kernel_launch(void* const* d_in, const int* in_sizes, int n_in,
                              void* d_out, int out_size) {
    const float* inp  = (const float*)d_in[0];   // [16384, 3072]
    const float* prev = (const float*)d_in[1];   // [16384, 1024]
    const float* mask = (const float*)d_in[2];   // [16384]
    const float* Wur  = (const float*)d_in[3];   // [1024, 2048]
    const float* U    = (const float*)d_in[4];   // [1024, 1024]
    float* out = (float*)d_out;                  // [16384, 1024]

    cudaFuncSetAttribute(ggru_gemm1, cudaFuncAttributeMaxDynamicSharedMemorySize, SMEM_TOTAL);
    cudaFuncSetAttribute(ggru_gemm2, cudaFuncAttributeMaxDynamicSharedMemorySize, SMEM_TOTAL);

    ggru_transpose<<<dim3(32, 32, 2), 256>>>(Wur, U);
    dim3 grid(H / BN, BATCH / BM);               // (8, 128) = 1024 CTAs
    ggru_gemm1<<<grid, 256, SMEM_TOTAL>>>(prev, inp);
    ggru_gemm2<<<grid, 256, SMEM_TOTAL>>>(inp, prev, mask, out);
}